// round 8
// baseline (speedup 1.0000x reference)
#include <cuda_runtime.h>
#include <cuda_fp16.h>
#include <mma.h>
#include <cstdint>

using namespace nvcuda;

#define IN_FEAT   64
#define OUT_FEAT  64
#define MAX_NODES 100000
#define MAX_EDGES 1600000
#define NB_SCAN   ((MAX_NODES + 255) / 256)   // 391

#define SA_LD 72   // half ld (mult of 8)
#define SC_LD 68   // float ld (mult of 4)

// Scratch (__device__ globals: allocation-free, zero-initialized at load)
__device__ __half2      g_h16[MAX_NODES * 32];   // h in fp16 (12.8 MB)
__device__ int          g_cnt[MAX_NODES];        // histogram (zero-invariant)
__device__ int          g_off[MAX_NODES + 1];    // CSR offsets
__device__ int          g_cur[MAX_NODES];        // scatter cursors
__device__ unsigned int g_state[NB_SCAN];        // lookback: (flag<<30)|value, UNSIGNED
__device__ int2         g_pair[MAX_EDGES];       // dst-sorted (src, att)

// ---------------------------------------------------------------------------
// Kernel 1: h = feat @ W + b -> fp16, via HMMA (wmma 16x16x16, fp32 accum).
// Block = 256 thr = 8 warps; tile 128 rows x 64 cols; warp owns 16 rows.
// ---------------------------------------------------------------------------
__global__ __launch_bounds__(256) void gemm_kernel(
    const float* __restrict__ feat,
    const float* __restrict__ W,
    const float* __restrict__ bias,
    __half2* __restrict__ h16,
    int n_nodes)
{
    extern __shared__ char smem[];
    __half (*sA)[SA_LD] = reinterpret_cast<__half(*)[SA_LD]>(smem);
    __half (*sB)[SA_LD] = reinterpret_cast<__half(*)[SA_LD]>(smem + 128 * SA_LD * 2);
    float*  sBias       = reinterpret_cast<float*>(smem + (128 + 64) * SA_LD * 2);
    float (*sC)[16][SC_LD] =
        reinterpret_cast<float(*)[16][SC_LD]>(smem + (128 + 64) * SA_LD * 2 + 256);

    const int tid  = threadIdx.x;
    const int row0 = blockIdx.x * 128;

    // stage W -> sB (fp16)
    {
        int k = tid >> 2, c4 = tid & 3;
        const float4* ws = reinterpret_cast<const float4*>(W + k * OUT_FEAT + c4 * 16);
#pragma unroll
        for (int i = 0; i < 4; i++) {
            float4 v = ws[i];
            int c = c4 * 16 + i * 4;
            sB[k][c + 0] = __float2half(v.x); sB[k][c + 1] = __float2half(v.y);
            sB[k][c + 2] = __float2half(v.z); sB[k][c + 3] = __float2half(v.w);
        }
    }
    if (tid < OUT_FEAT) sBias[tid] = bias[tid];

    // stage feat -> sA (fp16); zero-fill OOB rows
    {
        int rl = tid >> 1, hf = tid & 1;
        int grow = row0 + rl;
        const float* fr = feat + (size_t)grow * IN_FEAT + hf * 32;
#pragma unroll
        for (int i = 0; i < 8; i++) {
            float4 v = (grow < n_nodes)
                ? *reinterpret_cast<const float4*>(fr + i * 4)
                : make_float4(0.f, 0.f, 0.f, 0.f);
            int c = hf * 32 + i * 4;
            sA[rl][c + 0] = __float2half(v.x); sA[rl][c + 1] = __float2half(v.y);
            sA[rl][c + 2] = __float2half(v.z); sA[rl][c + 3] = __float2half(v.w);
        }
    }
    __syncthreads();

    const int w    = tid >> 5;
    const int lane = tid & 31;

    wmma::fragment<wmma::accumulator, 16, 16, 16, float> c[4];
#pragma unroll
    for (int n = 0; n < 4; n++) wmma::fill_fragment(c[n], 0.0f);

#pragma unroll
    for (int k = 0; k < 4; k++) {
        wmma::fragment<wmma::matrix_a, 16, 16, 16, __half, wmma::row_major> a;
        wmma::load_matrix_sync(a, &sA[w * 16][k * 16], SA_LD);
#pragma unroll
        for (int n = 0; n < 4; n++) {
            wmma::fragment<wmma::matrix_b, 16, 16, 16, __half, wmma::row_major> b;
            wmma::load_matrix_sync(b, &sB[k * 16][n * 16], SA_LD);
            wmma::mma_sync(c[n], a, b, c[n]);
        }
    }
#pragma unroll
    for (int n = 0; n < 4; n++)
        wmma::store_matrix_sync(&sC[w][0][n * 16], c[n], SC_LD, wmma::mem_row_major);
    __syncwarp();

    // epilogue: bias add, fp16 pack, coalesced store
    int rr = lane >> 1, hf = lane & 1;
    int grow = row0 + w * 16 + rr;
    if (grow < n_nodes) {
#pragma unroll
        for (int i = 0; i < 8; i++) {
            int col = hf * 32 + i * 4;
            float x0 = sC[w][rr][col + 0] + sBias[col + 0];
            float x1 = sC[w][rr][col + 1] + sBias[col + 1];
            float x2 = sC[w][rr][col + 2] + sBias[col + 2];
            float x3 = sC[w][rr][col + 3] + sBias[col + 3];
            __half2 p0 = __floats2half2_rn(x0, x1);
            __half2 p1 = __floats2half2_rn(x2, x3);
            uint2 u;
            u.x = *reinterpret_cast<uint32_t*>(&p0);
            u.y = *reinterpret_cast<uint32_t*>(&p1);
            *reinterpret_cast<uint2*>(h16 + (size_t)grow * 32 + col / 2) = u;
        }
    }
}

#define GEMM_SMEM ((128 + 64) * SA_LD * 2 + 256 + 8 * 16 * SC_LD * 4)

// ---------------------------------------------------------------------------
// hist: count edges per dst (g_cnt zero on entry — invariant).
// Block 0 also zeroes the lookback state array (consumed by next kernel,
// separated by a kernel boundary so ordering is guaranteed).
// ---------------------------------------------------------------------------
__global__ void hist_kernel(const int* __restrict__ dst, int n_edges)
{
    if (blockIdx.x == 0)
        for (int i = threadIdx.x; i < NB_SCAN; i += blockDim.x) g_state[i] = 0u;
    int e = blockIdx.x * blockDim.x + threadIdx.x;
    if (e < n_edges) atomicAdd(&g_cnt[dst[e]], 1);
}

// ---------------------------------------------------------------------------
// scan: single-pass decoupled lookback over UNSIGNED packed words.
// flag: 0=empty, 1=aggregate, 2=inclusive prefix; value <= 1.6M < 2^30 so
// (flag<<30)|value is one word -> same-word atomicity, no fences needed.
// Lookback only waits on lower block ids (launched earlier; all 391 blocks
// fit in wave 1). Re-zeroes g_cnt, inits cursors, writes g_off[n].
// ---------------------------------------------------------------------------
__global__ __launch_bounds__(256) void scan_kernel(int n, int n_edges)
{
    __shared__ int wsum[8];
    __shared__ int sPrefix;

    int b    = blockIdx.x;
    int i    = b * 256 + threadIdx.x;
    int lane = threadIdx.x & 31;
    int wid  = threadIdx.x >> 5;
    int v    = (i < n) ? g_cnt[i] : 0;
    if (i < n) g_cnt[i] = 0;              // restore zero-invariant

    int x = v;
#pragma unroll
    for (int off = 1; off < 32; off <<= 1) {
        int t = __shfl_up_sync(0xffffffff, x, off);
        if (lane >= off) x += t;
    }
    if (lane == 31) wsum[wid] = x;
    __syncthreads();
    if (wid == 0) {
        int s = (lane < 8) ? wsum[lane] : 0;
#pragma unroll
        for (int off = 1; off < 8; off <<= 1) {
            int t = __shfl_up_sync(0xffffffff, s, off);
            if (lane >= off) s += t;
        }
        if (lane < 8) wsum[lane] = s;
    }
    __syncthreads();
    int incl = x + (wid > 0 ? wsum[wid - 1] : 0);   // block-local inclusive
    unsigned int agg = (unsigned int)wsum[7];       // block total

    if (threadIdx.x == 0) {
        volatile unsigned int* st = g_state;
        if (b == 0) {
            st[0] = (2u << 30) | agg;
            sPrefix = 0;
        } else {
            st[b] = (1u << 30) | agg;
            unsigned int run = 0u;
            int idx = b - 1;
            while (true) {
                unsigned int s;
                do { s = st[idx]; } while ((s >> 30) == 0u);
                run += s & 0x3FFFFFFFu;
                if ((s >> 30) == 2u) break;
                idx--;
            }
            st[b] = (2u << 30) | (run + agg);
            sPrefix = (int)run;
        }
    }
    __syncthreads();
    int prefix = sPrefix;

    if (i < n) {
        int excl = incl - v + prefix;
        g_off[i] = excl;
        g_cur[i] = excl;
    }
    if (i == n - 1) g_off[n] = prefix + incl;   // == n_edges
}

// ---------------------------------------------------------------------------
// perm: place packed (src, att) pairs in dst-sorted order
// ---------------------------------------------------------------------------
__global__ void perm_kernel(const int* __restrict__ src,
                            const int* __restrict__ dst,
                            const float* __restrict__ att,
                            int n_edges)
{
    int e = blockIdx.x * blockDim.x + threadIdx.x;
    if (e >= n_edges) return;
    int d = dst[e];
    int p = atomicAdd(&g_cur[d], 1);
    g_pair[p] = make_int2(src[e], __float_as_int(att[e]));
}

// ---------------------------------------------------------------------------
// accum: one warp per dst node; lane owns 2 cols; fp32 accumulation.
// ---------------------------------------------------------------------------
__global__ __launch_bounds__(256) void accum_kernel(
    const __half2* __restrict__ h16,
    float* __restrict__ out,
    int n_nodes)
{
    int warp = (blockIdx.x * 256 + threadIdx.x) >> 5;
    int lane = threadIdx.x & 31;
    if (warp >= n_nodes) return;

    int j   = g_off[warp];
    int end = g_off[warp + 1];

    float2 acc = make_float2(0.f, 0.f);

    for (; j + 3 < end; j += 4) {
        int2 p0 = __ldg(&g_pair[j]);
        int2 p1 = __ldg(&g_pair[j + 1]);
        int2 p2 = __ldg(&g_pair[j + 2]);
        int2 p3 = __ldg(&g_pair[j + 3]);
        float2 v0 = __half22float2(__ldg(h16 + (size_t)p0.x * 32 + lane));
        float2 v1 = __half22float2(__ldg(h16 + (size_t)p1.x * 32 + lane));
        float2 v2 = __half22float2(__ldg(h16 + (size_t)p2.x * 32 + lane));
        float2 v3 = __half22float2(__ldg(h16 + (size_t)p3.x * 32 + lane));
        float a0 = __int_as_float(p0.y), a1 = __int_as_float(p1.y);
        float a2 = __int_as_float(p2.y), a3 = __int_as_float(p3.y);
        acc.x = fmaf(a0, v0.x, acc.x); acc.y = fmaf(a0, v0.y, acc.y);
        acc.x = fmaf(a1, v1.x, acc.x); acc.y = fmaf(a1, v1.y, acc.y);
        acc.x = fmaf(a2, v2.x, acc.x); acc.y = fmaf(a2, v2.y, acc.y);
        acc.x = fmaf(a3, v3.x, acc.x); acc.y = fmaf(a3, v3.y, acc.y);
    }
    for (; j < end; j++) {
        int2 p = __ldg(&g_pair[j]);
        float a = __int_as_float(p.y);
        float2 v = __half22float2(__ldg(h16 + (size_t)p.x * 32 + lane));
        acc.x = fmaf(a, v.x, acc.x);
        acc.y = fmaf(a, v.y, acc.y);
    }

    *reinterpret_cast<float2*>(out + (size_t)warp * OUT_FEAT + lane * 2) = acc;
}

// ---------------------------------------------------------------------------
// Launch: GEMM forked onto side stream, concurrent with binning chain.
// ---------------------------------------------------------------------------
extern "C" void kernel_launch(void* const* d_in, const int* in_sizes, int n_in,
                              void* d_out, int out_size)
{
    const float* feat = (const float*)d_in[0];
    const float* att  = (const float*)d_in[1];
    const int*   src  = (const int*)  d_in[2];
    const int*   dst  = (const int*)  d_in[3];
    const float* W    = (const float*)d_in[4];
    const float* bias = (const float*)d_in[5];
    float*       out  = (float*)d_out;

    int n_nodes = in_sizes[0] / IN_FEAT;
    int n_edges = in_sizes[2];

    __half2* h16;
    cudaGetSymbolAddress((void**)&h16, g_h16);

    cudaFuncSetAttribute(gemm_kernel,
                         cudaFuncAttributeMaxDynamicSharedMemorySize, GEMM_SMEM);

    cudaStream_t side;
    cudaStreamCreateWithFlags(&side, cudaStreamNonBlocking);
    cudaEvent_t evFork, evJoin;
    cudaEventCreateWithFlags(&evFork, cudaEventDisableTiming);
    cudaEventCreateWithFlags(&evJoin, cudaEventDisableTiming);

    // fork: gemm on side stream
    cudaEventRecord(evFork, 0);
    cudaStreamWaitEvent(side, evFork, 0);
    gemm_kernel<<<(n_nodes + 127) / 128, 256, GEMM_SMEM, side>>>(feat, W, bias, h16, n_nodes);
    cudaEventRecord(evJoin, side);

    // binning chain on main stream
    hist_kernel<<<(n_edges + 255) / 256, 256>>>(dst, n_edges);
    scan_kernel<<<NB_SCAN, 256>>>(n_nodes, n_edges);
    perm_kernel<<<(n_edges + 255) / 256, 256>>>(src, dst, att, n_edges);

    // join, then accumulate
    cudaStreamWaitEvent(0, evJoin, 0);
    long long work = (long long)n_nodes * 32;
    accum_kernel<<<(int)((work + 255) / 256), 256>>>(h16, out, n_nodes);
}

// round 9
// speedup vs baseline: 1.1083x; 1.1083x over previous
#include <cuda_runtime.h>
#include <cuda_fp16.h>
#include <mma.h>
#include <cstdint>

using namespace nvcuda;

#define IN_FEAT   64
#define OUT_FEAT  64
#define MAX_NODES 100000
#define MAX_EDGES 1600000
#define NB_SCAN   ((MAX_NODES + 255) / 256)   // 391

#define SA_LD 72   // half ld (mult of 8)
#define SC_LD 68   // float ld (mult of 4)

// Scratch (__device__ globals: allocation-free, zero-initialized at load)
__device__ __half2      g_h16[MAX_NODES * 32];   // h in fp16 (12.8 MB)
__device__ int          g_cnt[MAX_NODES];        // histogram (zero-invariant)
__device__ int          g_off[MAX_NODES + 1];    // CSR offsets
__device__ int          g_rank[MAX_EDGES];       // per-edge rank within its dst
__device__ unsigned int g_state[NB_SCAN];        // lookback: (flag<<30)|value
__device__ int2         g_pair[MAX_EDGES];       // dst-sorted (src, att)

// ---------------------------------------------------------------------------
// Kernel 1: h = feat @ W + b -> fp16, via HMMA (wmma 16x16x16, fp32 accum).
// ---------------------------------------------------------------------------
__global__ __launch_bounds__(256) void gemm_kernel(
    const float* __restrict__ feat,
    const float* __restrict__ W,
    const float* __restrict__ bias,
    __half2* __restrict__ h16,
    int n_nodes)
{
    extern __shared__ char smem[];
    __half (*sA)[SA_LD] = reinterpret_cast<__half(*)[SA_LD]>(smem);
    __half (*sB)[SA_LD] = reinterpret_cast<__half(*)[SA_LD]>(smem + 128 * SA_LD * 2);
    float*  sBias       = reinterpret_cast<float*>(smem + (128 + 64) * SA_LD * 2);
    float (*sC)[16][SC_LD] =
        reinterpret_cast<float(*)[16][SC_LD]>(smem + (128 + 64) * SA_LD * 2 + 256);

    const int tid  = threadIdx.x;
    const int row0 = blockIdx.x * 128;

    {
        int k = tid >> 2, c4 = tid & 3;
        const float4* ws = reinterpret_cast<const float4*>(W + k * OUT_FEAT + c4 * 16);
#pragma unroll
        for (int i = 0; i < 4; i++) {
            float4 v = ws[i];
            int c = c4 * 16 + i * 4;
            sB[k][c + 0] = __float2half(v.x); sB[k][c + 1] = __float2half(v.y);
            sB[k][c + 2] = __float2half(v.z); sB[k][c + 3] = __float2half(v.w);
        }
    }
    if (tid < OUT_FEAT) sBias[tid] = bias[tid];

    {
        int rl = tid >> 1, hf = tid & 1;
        int grow = row0 + rl;
        const float* fr = feat + (size_t)grow * IN_FEAT + hf * 32;
#pragma unroll
        for (int i = 0; i < 8; i++) {
            float4 v = (grow < n_nodes)
                ? *reinterpret_cast<const float4*>(fr + i * 4)
                : make_float4(0.f, 0.f, 0.f, 0.f);
            int c = hf * 32 + i * 4;
            sA[rl][c + 0] = __float2half(v.x); sA[rl][c + 1] = __float2half(v.y);
            sA[rl][c + 2] = __float2half(v.z); sA[rl][c + 3] = __float2half(v.w);
        }
    }
    __syncthreads();

    const int w    = tid >> 5;
    const int lane = tid & 31;

    wmma::fragment<wmma::accumulator, 16, 16, 16, float> c[4];
#pragma unroll
    for (int n = 0; n < 4; n++) wmma::fill_fragment(c[n], 0.0f);

#pragma unroll
    for (int k = 0; k < 4; k++) {
        wmma::fragment<wmma::matrix_a, 16, 16, 16, __half, wmma::row_major> a;
        wmma::load_matrix_sync(a, &sA[w * 16][k * 16], SA_LD);
#pragma unroll
        for (int n = 0; n < 4; n++) {
            wmma::fragment<wmma::matrix_b, 16, 16, 16, __half, wmma::row_major> b;
            wmma::load_matrix_sync(b, &sB[k * 16][n * 16], SA_LD);
            wmma::mma_sync(c[n], a, b, c[n]);
        }
    }
#pragma unroll
    for (int n = 0; n < 4; n++)
        wmma::store_matrix_sync(&sC[w][0][n * 16], c[n], SC_LD, wmma::mem_row_major);
    __syncwarp();

    int rr = lane >> 1, hf = lane & 1;
    int grow = row0 + w * 16 + rr;
    if (grow < n_nodes) {
#pragma unroll
        for (int i = 0; i < 8; i++) {
            int col = hf * 32 + i * 4;
            float x0 = sC[w][rr][col + 0] + sBias[col + 0];
            float x1 = sC[w][rr][col + 1] + sBias[col + 1];
            float x2 = sC[w][rr][col + 2] + sBias[col + 2];
            float x3 = sC[w][rr][col + 3] + sBias[col + 3];
            __half2 p0 = __floats2half2_rn(x0, x1);
            __half2 p1 = __floats2half2_rn(x2, x3);
            uint2 u;
            u.x = *reinterpret_cast<uint32_t*>(&p0);
            u.y = *reinterpret_cast<uint32_t*>(&p1);
            *reinterpret_cast<uint2*>(h16 + (size_t)grow * 32 + col / 2) = u;
        }
    }
}

#define GEMM_SMEM ((128 + 64) * SA_LD * 2 + 256 + 8 * 16 * SC_LD * 4)

// ---------------------------------------------------------------------------
// hist: count edges per dst AND record each edge's rank within its dst
// (the atomicAdd return value). g_cnt zero on entry — invariant.
// Block 0 zeroes the lookback state (consumed next kernel).
// ---------------------------------------------------------------------------
__global__ void hist_kernel(const int* __restrict__ dst, int n_edges)
{
    if (blockIdx.x == 0)
        for (int i = threadIdx.x; i < NB_SCAN; i += blockDim.x) g_state[i] = 0u;
    int e = blockIdx.x * blockDim.x + threadIdx.x;
    if (e < n_edges) g_rank[e] = atomicAdd(&g_cnt[dst[e]], 1);
}

// ---------------------------------------------------------------------------
// scan: single-pass decoupled lookback, WARP-PARALLEL window (32 statuses
// per step, ballot for nearest PREFIX). flag: 0=empty,1=agg,2=prefix;
// value < 2^30 so one packed word = same-word atomicity, no fences.
// Re-zeroes g_cnt; writes g_off (exclusive) and g_off[n].
// ---------------------------------------------------------------------------
__global__ __launch_bounds__(256) void scan_kernel(int n, int n_edges)
{
    __shared__ int wsum[8];
    __shared__ int sPrefix;

    int b    = blockIdx.x;
    int i    = b * 256 + threadIdx.x;
    int lane = threadIdx.x & 31;
    int wid  = threadIdx.x >> 5;
    int v    = (i < n) ? g_cnt[i] : 0;
    if (i < n) g_cnt[i] = 0;              // restore zero-invariant

    int x = v;
#pragma unroll
    for (int off = 1; off < 32; off <<= 1) {
        int t = __shfl_up_sync(0xffffffff, x, off);
        if (lane >= off) x += t;
    }
    if (lane == 31) wsum[wid] = x;
    __syncthreads();
    if (wid == 0) {
        int s = (lane < 8) ? wsum[lane] : 0;
#pragma unroll
        for (int off = 1; off < 8; off <<= 1) {
            int t = __shfl_up_sync(0xffffffff, s, off);
            if (lane >= off) s += t;
        }
        if (lane < 8) wsum[lane] = s;
    }
    __syncthreads();
    int incl = x + (wid > 0 ? wsum[wid - 1] : 0);
    unsigned int agg = (unsigned int)wsum[7];

    // warp 0: publish aggregate, then warp-parallel lookback
    if (wid == 0) {
        volatile unsigned int* st = g_state;
        if (b == 0) {
            if (lane == 0) { st[0] = (2u << 30) | agg; sPrefix = 0; }
        } else {
            if (lane == 0) st[b] = (1u << 30) | agg;
            __syncwarp();
            unsigned int run = 0u;
            int idx = b - 1;
            while (true) {
                int my = idx - lane;                   // lane 0 = closest to b
                unsigned int s;
                do {
                    s = (my >= 0) ? st[my] : ((1u << 30) | 0u);
                } while ((s >> 30) == 0u);
                unsigned int flag = s >> 30;
                unsigned int ball = __ballot_sync(0xffffffff, flag == 2u);
                unsigned int val  = s & 0x3FFFFFFFu;
                if (ball) {
                    int lead = __ffs(ball) - 1;        // nearest PREFIX
                    unsigned int contrib = (lane <= lead) ? val : 0u;
#pragma unroll
                    for (int o = 16; o > 0; o >>= 1)
                        contrib += __shfl_down_sync(0xffffffff, contrib, o);
                    run += __shfl_sync(0xffffffff, contrib, 0);
                    break;
                } else {
                    unsigned int contrib = (my >= 0) ? val : 0u;
#pragma unroll
                    for (int o = 16; o > 0; o >>= 1)
                        contrib += __shfl_down_sync(0xffffffff, contrib, o);
                    run += __shfl_sync(0xffffffff, contrib, 0);
                    idx -= 32;
                }
            }
            if (lane == 0) {
                st[b] = (2u << 30) | (run + agg);
                sPrefix = (int)run;
            }
        }
    }
    __syncthreads();
    int prefix = sPrefix;

    if (i < n) g_off[i] = incl - v + prefix;
    if (i == n - 1) g_off[n] = prefix + incl;   // == n_edges
}

// ---------------------------------------------------------------------------
// perm: atomic-free placement using precomputed rank.
// ---------------------------------------------------------------------------
__global__ void perm_kernel(const int* __restrict__ src,
                            const int* __restrict__ dst,
                            const float* __restrict__ att,
                            int n_edges)
{
    int e = blockIdx.x * blockDim.x + threadIdx.x;
    if (e >= n_edges) return;
    int p = g_off[dst[e]] + g_rank[e];
    g_pair[p] = make_int2(src[e], __float_as_int(att[e]));
}

// ---------------------------------------------------------------------------
// accum: one warp per dst node; lane owns 2 cols; fp32 accumulation.
// ---------------------------------------------------------------------------
__global__ __launch_bounds__(256) void accum_kernel(
    const __half2* __restrict__ h16,
    float* __restrict__ out,
    int n_nodes)
{
    int warp = (blockIdx.x * 256 + threadIdx.x) >> 5;
    int lane = threadIdx.x & 31;
    if (warp >= n_nodes) return;

    int j   = g_off[warp];
    int end = g_off[warp + 1];

    float2 acc = make_float2(0.f, 0.f);

    for (; j + 3 < end; j += 4) {
        int2 p0 = __ldg(&g_pair[j]);
        int2 p1 = __ldg(&g_pair[j + 1]);
        int2 p2 = __ldg(&g_pair[j + 2]);
        int2 p3 = __ldg(&g_pair[j + 3]);
        float2 v0 = __half22float2(__ldg(h16 + (size_t)p0.x * 32 + lane));
        float2 v1 = __half22float2(__ldg(h16 + (size_t)p1.x * 32 + lane));
        float2 v2 = __half22float2(__ldg(h16 + (size_t)p2.x * 32 + lane));
        float2 v3 = __half22float2(__ldg(h16 + (size_t)p3.x * 32 + lane));
        float a0 = __int_as_float(p0.y), a1 = __int_as_float(p1.y);
        float a2 = __int_as_float(p2.y), a3 = __int_as_float(p3.y);
        acc.x = fmaf(a0, v0.x, acc.x); acc.y = fmaf(a0, v0.y, acc.y);
        acc.x = fmaf(a1, v1.x, acc.x); acc.y = fmaf(a1, v1.y, acc.y);
        acc.x = fmaf(a2, v2.x, acc.x); acc.y = fmaf(a2, v2.y, acc.y);
        acc.x = fmaf(a3, v3.x, acc.x); acc.y = fmaf(a3, v3.y, acc.y);
    }
    for (; j < end; j++) {
        int2 p = __ldg(&g_pair[j]);
        float a = __int_as_float(p.y);
        float2 v = __half22float2(__ldg(h16 + (size_t)p.x * 32 + lane));
        acc.x = fmaf(a, v.x, acc.x);
        acc.y = fmaf(a, v.y, acc.y);
    }

    *reinterpret_cast<float2*>(out + (size_t)warp * OUT_FEAT + lane * 2) = acc;
}

// ---------------------------------------------------------------------------
// Launch: GEMM forked onto side stream, concurrent with binning chain.
// ---------------------------------------------------------------------------
extern "C" void kernel_launch(void* const* d_in, const int* in_sizes, int n_in,
                              void* d_out, int out_size)
{
    const float* feat = (const float*)d_in[0];
    const float* att  = (const float*)d_in[1];
    const int*   src  = (const int*)  d_in[2];
    const int*   dst  = (const int*)  d_in[3];
    const float* W    = (const float*)d_in[4];
    const float* bias = (const float*)d_in[5];
    float*       out  = (float*)d_out;

    int n_nodes = in_sizes[0] / IN_FEAT;
    int n_edges = in_sizes[2];

    __half2* h16;
    cudaGetSymbolAddress((void**)&h16, g_h16);

    cudaFuncSetAttribute(gemm_kernel,
                         cudaFuncAttributeMaxDynamicSharedMemorySize, GEMM_SMEM);

    cudaStream_t side;
    cudaStreamCreateWithFlags(&side, cudaStreamNonBlocking);
    cudaEvent_t evFork, evJoin;
    cudaEventCreateWithFlags(&evFork, cudaEventDisableTiming);
    cudaEventCreateWithFlags(&evJoin, cudaEventDisableTiming);

    // fork: gemm on side stream
    cudaEventRecord(evFork, 0);
    cudaStreamWaitEvent(side, evFork, 0);
    gemm_kernel<<<(n_nodes + 127) / 128, 256, GEMM_SMEM, side>>>(feat, W, bias, h16, n_nodes);
    cudaEventRecord(evJoin, side);

    // binning chain on main stream
    hist_kernel<<<(n_edges + 255) / 256, 256>>>(dst, n_edges);
    scan_kernel<<<NB_SCAN, 256>>>(n_nodes, n_edges);
    perm_kernel<<<(n_edges + 255) / 256, 256>>>(src, dst, att, n_edges);

    // join, then accumulate
    cudaStreamWaitEvent(0, evJoin, 0);
    long long work = (long long)n_nodes * 32;
    accum_kernel<<<(int)((work + 255) / 256), 256>>>(h16, out, n_nodes);
}